// round 2
// baseline (speedup 1.0000x reference)
#include <cuda_runtime.h>
#include <cuda_bf16.h>

// DWT_1D: lo/hi[n,c,k] = sum_{j=0..7} tap[j] * x[n,c, 2k+j-3], zero outside [0,SEQ)
// x: (16,64,8192) f32; out: lo (16,64,4096) then hi (16,64,4096), f32.
// Taps read from banded matrices: matrix_low[2, 1+j] == REC_LO[j].

namespace {
constexpr int SEQ  = 8192;
constexpr int KOUT = 4096;
constexpr int NC   = 16 * 64;         // 1024 rows
constexpr int TPB  = 256;
constexpr int GPR  = KOUT / 8;        // 512 output-groups (of 8) per row
constexpr int S4   = SEQ / 4;         // 2048 float4 per row
}

__global__ __launch_bounds__(TPB)
void dwt1d_kernel(const float4* __restrict__ x4,
                  const float* __restrict__ mlo,
                  const float* __restrict__ mhi,
                  float* __restrict__ out)
{
    const int u   = blockIdx.x * TPB + threadIdx.x;   // 0 .. NC*GPR-1
    const int row = u >> 9;                            // /512
    const int gl  = u & (GPR - 1);                     // group within row

    const float4* __restrict__ xr = x4 + (size_t)row * S4;

    // Window: x[16gl-4 .. 16gl+19] as 6 float4 loads (idx 4gl-1 .. 4gl+4).
    // Only the first/last group of a row can go out of range.
    float w[24];
    const int j0 = 4 * gl - 1;
    #pragma unroll
    for (int i = 0; i < 6; ++i) {
        const int j = j0 + i;
        float4 v;
        if (j >= 0 && j < S4) v = xr[j];
        else                  v = make_float4(0.f, 0.f, 0.f, 0.f);
        w[4*i + 0] = v.x; w[4*i + 1] = v.y; w[4*i + 2] = v.z; w[4*i + 3] = v.w;
    }

    // Filter taps from the banded matrices (row 2, cols 1..8) — uniform L1 broadcast.
    float h[8], g[8];
    #pragma unroll
    for (int j = 0; j < 8; ++j) {
        h[j] = __ldg(&mlo[2 * SEQ + 1 + j]);
        g[j] = __ldg(&mhi[2 * SEQ + 1 + j]);
    }

    // Outputs k = 8gl + p, p = 0..7; input x[16gl + 2p - 3 + j] = w[2p + 1 + j].
    float lo[8], hi[8];
    #pragma unroll
    for (int p = 0; p < 8; ++p) {
        float a = 0.f, b = 0.f;
        #pragma unroll
        for (int j = 0; j < 8; ++j) {
            const float xv = w[2*p + 1 + j];
            a = fmaf(h[j], xv, a);
            b = fmaf(g[j], xv, b);
        }
        lo[p] = a; hi[p] = b;
    }

    float4* __restrict__ lo4 = reinterpret_cast<float4*>(out + (size_t)row * KOUT) + 2 * gl;
    float4* __restrict__ hi4 = reinterpret_cast<float4*>(out + (size_t)NC * KOUT + (size_t)row * KOUT) + 2 * gl;
    lo4[0] = make_float4(lo[0], lo[1], lo[2], lo[3]);
    lo4[1] = make_float4(lo[4], lo[5], lo[6], lo[7]);
    hi4[0] = make_float4(hi[0], hi[1], hi[2], hi[3]);
    hi4[1] = make_float4(hi[4], hi[5], hi[6], hi[7]);
}

extern "C" void kernel_launch(void* const* d_in, const int* in_sizes, int n_in,
                              void* d_out, int out_size)
{
    const float4* x  = (const float4*)d_in[0];
    const float* mlo = (const float*)d_in[1];
    const float* mhi = (const float*)d_in[2];
    float* out = (float*)d_out;

    dwt1d_kernel<<<(NC * GPR) / TPB, TPB>>>(x, mlo, mhi, out);
}